// round 2
// baseline (speedup 1.0000x reference)
#include <cuda_runtime.h>
#include <math.h>

#define N_NODES   100000
#define E_EDGES   1600000
#define W_IN      256
#define W_OUT     128
#define NUM_TYPES 4
#define K_STEPS   10
#define ALPHA_F   0.1f
#define EPS_F     1e-12f
#define TOTAL_NNZ (E_EDGES + N_NODES)
#define SCAN_B    1024
#define NB_SCAN   ((N_NODES + SCAN_B - 1) / SCAN_B)

// ---------------- scratch (device globals; no allocation) ----------------
__device__ float d_H[N_NODES * W_OUT];
__device__ float d_tilde[N_NODES * W_OUT];
__device__ float d_z[N_NODES * W_OUT];
__device__ float d_hA[N_NODES * W_OUT];
__device__ float d_hB[N_NODES * W_OUT];
__device__ int   d_deg[N_NODES];
__device__ int   d_cursor[N_NODES];
__device__ int   d_rowptr[N_NODES + 1];
__device__ int   d_bsum[NB_SCAN];
__device__ int   d_boff[NB_SCAN];
__device__ float d_dinv[N_NODES];
__device__ int   d_col[TOTAL_NNZ];
__device__ float d_val[TOTAL_NNZ];
__device__ float d_tsum[NUM_TYPES * W_OUT];
__device__ float d_tsq[NUM_TYPES * W_OUT];
__device__ float d_tcnt[NUM_TYPES];
__device__ float d_mean[NUM_TYPES * W_OUT];
__device__ float d_std[NUM_TYPES * W_OUT];
__device__ double d_posAcc;
__device__ double d_negAcc;

// ---------------- init (runs every launch; graph-replay safe) ----------------
__global__ void init_kernel() {
    int i = blockIdx.x * blockDim.x + threadIdx.x;
    if (i < N_NODES) { d_deg[i] = 1; d_cursor[i] = 0; }   // deg starts at 1 (self loop)
    if (i < NUM_TYPES * W_OUT) { d_tsum[i] = 0.f; d_tsq[i] = 0.f; }
    if (i < NUM_TYPES) d_tcnt[i] = 0.f;
    if (i == 0) { d_posAcc = 0.0; d_negAcc = 0.0; }
}

// ---------------- GEMM + bias + row l2norm -> H ----------------
// block: 256 threads; 64 nodes/block; thread = (node-group 0..7) x (feat-group 0..31, 4 feats)
#define GB_NODES 64
#define GB_CHUNK 32
__global__ void gemm_l2norm_kernel(const float* __restrict__ X,
                                   const float* __restrict__ W,
                                   const float* __restrict__ b) {
    __shared__ float Ws[GB_CHUNK][W_OUT];         // 16 KB
    __shared__ float Xs[GB_NODES][GB_CHUNK + 1];  // ~8.4 KB
    int tid = threadIdx.x;
    int fg  = tid & 31;   // features 4*fg .. 4*fg+3
    int ng  = tid >> 5;   // node group 0..7
    int nodeBase = blockIdx.x * GB_NODES;

    float4 acc[8];
#pragma unroll
    for (int i = 0; i < 8; i++) acc[i] = make_float4(0.f, 0.f, 0.f, 0.f);

    for (int kc = 0; kc < W_IN; kc += GB_CHUNK) {
#pragma unroll
        for (int j = 0; j < (GB_CHUNK * W_OUT) / 256; j++) {
            int idx = tid + j * 256;
            int kk = idx >> 7, ff = idx & 127;
            Ws[kk][ff] = W[(kc + kk) * W_OUT + ff];
        }
        {
            int kk = tid & 31;
            int r0 = tid >> 5;
#pragma unroll
            for (int j = 0; j < 8; j++) {
                int r = r0 + j * 8;
                int node = nodeBase + r;
                Xs[r][kk] = (node < N_NODES) ? X[node * W_IN + kc + kk] : 0.f;
            }
        }
        __syncthreads();
#pragma unroll
        for (int kk = 0; kk < GB_CHUNK; kk++) {
            float4 w4 = *reinterpret_cast<const float4*>(&Ws[kk][fg * 4]);
#pragma unroll
            for (int i = 0; i < 8; i++) {
                float x = Xs[ng + i * 8][kk];
                acc[i].x += x * w4.x; acc[i].y += x * w4.y;
                acc[i].z += x * w4.z; acc[i].w += x * w4.w;
            }
        }
        __syncthreads();
    }

    float4 b4 = *reinterpret_cast<const float4*>(&b[fg * 4]);
#pragma unroll
    for (int i = 0; i < 8; i++) {
        int node = nodeBase + ng + i * 8;
        float4 h;
        h.x = acc[i].x + b4.x; h.y = acc[i].y + b4.y;
        h.z = acc[i].z + b4.z; h.w = acc[i].w + b4.w;
        float ss = h.x * h.x + h.y * h.y + h.z * h.z + h.w * h.w;
#pragma unroll
        for (int off = 16; off; off >>= 1) ss += __shfl_xor_sync(0xffffffffu, ss, off);
        float inv = 1.f / fmaxf(sqrtf(ss), EPS_F);
        if (node < N_NODES) {
            h.x *= inv; h.y *= inv; h.z *= inv; h.w *= inv;
            *reinterpret_cast<float4*>(&d_H[node * W_OUT + fg * 4]) = h;
        }
    }
}

// ---------------- per-type stats (sum, sumsq, count) ----------------
__global__ void stats_kernel(const int* __restrict__ nt) {
    int f = threadIdx.x;  // 128 threads = 128 features
    float sum[4] = {0, 0, 0, 0}, sq[4] = {0, 0, 0, 0}, cnt[4] = {0, 0, 0, 0};
    for (int node = blockIdx.x; node < N_NODES; node += gridDim.x) {
        int t = nt[node];
        float v = d_H[node * W_OUT + f];
#pragma unroll
        for (int tt = 0; tt < 4; tt++)
            if (tt == t) {
                sum[tt] += v; sq[tt] += v * v;
                if (f == 0) cnt[tt] += 1.f;
            }
    }
#pragma unroll
    for (int tt = 0; tt < 4; tt++) {
        atomicAdd(&d_tsum[tt * W_OUT + f], sum[tt]);
        atomicAdd(&d_tsq[tt * W_OUT + f], sq[tt]);
        if (f == 0) atomicAdd(&d_tcnt[tt], cnt[tt]);
    }
}

__global__ void finalize_stats_kernel() {
    int i = blockIdx.x * blockDim.x + threadIdx.x;
    if (i < NUM_TYPES * W_OUT) {
        int t = i / W_OUT;
        float c = d_tcnt[t];
        float m = d_tsum[i] / c;
        float var = (d_tsq[i] - c * m * m) / (c - 1.f);  // unbiased (torch.std)
        d_mean[i] = m;
        d_std[i] = sqrtf(fmaxf(var, 0.f));
    }
}

// ---------------- tilde_H + z (l2norm of tilde_H) ----------------
__global__ void tilde_kernel(const int* __restrict__ nt) {
    int w = (blockIdx.x * blockDim.x + threadIdx.x) >> 5;
    int lane = threadIdx.x & 31;
    if (w >= N_NODES) return;
    int t = nt[w];
    float4 h = *reinterpret_cast<const float4*>(&d_H[w * W_OUT + lane * 4]);
    float4 m = *reinterpret_cast<const float4*>(&d_mean[t * W_OUT + lane * 4]);
    float4 s = *reinterpret_cast<const float4*>(&d_std[t * W_OUT + lane * 4]);
    float4 td;
    td.x = (h.x - m.x) / s.x; td.y = (h.y - m.y) / s.y;
    td.z = (h.z - m.z) / s.z; td.w = (h.w - m.w) / s.w;
    *reinterpret_cast<float4*>(&d_tilde[w * W_OUT + lane * 4]) = td;
    float ss = td.x * td.x + td.y * td.y + td.z * td.z + td.w * td.w;
#pragma unroll
    for (int off = 16; off; off >>= 1) ss += __shfl_xor_sync(0xffffffffu, ss, off);
    float inv = 1.f / fmaxf(sqrtf(ss), EPS_F);
    float4 z = make_float4(td.x * inv, td.y * inv, td.z * inv, td.w * inv);
    *reinterpret_cast<float4*>(&d_z[w * W_OUT + lane * 4]) = z;
}

// ---------------- degree histogram (in-degree by dst; self loop pre-counted) ----------------
__global__ void deg_kernel(const int* __restrict__ dst) {
    int e = blockIdx.x * blockDim.x + threadIdx.x;
    if (e < E_EDGES) atomicAdd(&d_deg[dst[e]], 1);
}

// ---------------- exclusive prefix scan of deg -> rowptr (3 kernels) ----------------
__global__ void scan1_kernel() {
    __shared__ int s[SCAN_B];
    int tid = threadIdx.x;
    int i = blockIdx.x * SCAN_B + tid;
    int v = (i < N_NODES) ? d_deg[i] : 0;
    s[tid] = v;
    __syncthreads();
    for (int off = 1; off < SCAN_B; off <<= 1) {
        int t = (tid >= off) ? s[tid - off] : 0;
        __syncthreads();
        s[tid] += t;
        __syncthreads();
    }
    if (i < N_NODES) d_rowptr[i] = s[tid] - v;
    if (tid == SCAN_B - 1) d_bsum[blockIdx.x] = s[SCAN_B - 1];
}

__global__ void scan2_kernel() {
    if (threadIdx.x == 0) {
        int run = 0;
        for (int b = 0; b < NB_SCAN; b++) { d_boff[b] = run; run += d_bsum[b]; }
        d_rowptr[N_NODES] = run;
    }
}

__global__ void scan3_kernel() {
    int i = blockIdx.x * blockDim.x + threadIdx.x;
    if (i < N_NODES) {
        d_rowptr[i] += d_boff[i >> 10];
        d_dinv[i] = rsqrtf((float)d_deg[i]);
    }
}

// ---------------- CSR fill (edges + self loops) ----------------
__global__ void fill_kernel(const int* __restrict__ src, const int* __restrict__ dst) {
    int i = blockIdx.x * blockDim.x + threadIdx.x;
    if (i < E_EDGES) {
        int s = src[i], d = dst[i];
        int p = d_rowptr[d] + atomicAdd(&d_cursor[d], 1);
        d_col[p] = s;
        d_val[p] = d_dinv[s] * d_dinv[d];
    } else if (i < E_EDGES + N_NODES) {
        int n = i - E_EDGES;
        int p = d_rowptr[n] + atomicAdd(&d_cursor[n], 1);
        d_col[p] = n;
        d_val[p] = d_dinv[n] * d_dinv[n];
    }
}

// ---------------- APPNP step: h_out = (1-a) * A_hat h_in + a * tilde ----------------
// buffer selector: 0 = tilde, 1 = hA, 2 = hB
__device__ __forceinline__ float* buf_ptr(int sel) {
    return sel == 0 ? d_tilde : (sel == 1 ? d_hA : d_hB);
}

__global__ void appnp_kernel(int inSel, int outSel) {
    const float* __restrict__ hin = buf_ptr(inSel);
    float* __restrict__ hout = buf_ptr(outSel);
    int w = (blockIdx.x * blockDim.x + threadIdx.x) >> 5;
    int lane = threadIdx.x & 31;
    if (w >= N_NODES) return;
    int start = d_rowptr[w], end = d_rowptr[w + 1];
    float4 agg = make_float4(0.f, 0.f, 0.f, 0.f);
    for (int base = start; base < end; base += 32) {
        int j = base + lane;
        int c = 0; float v = 0.f;
        if (j < end) { c = d_col[j]; v = d_val[j]; }
        int m = min(32, end - base);
        for (int k = 0; k < m; k++) {
            int cc = __shfl_sync(0xffffffffu, c, k);
            float vv = __shfl_sync(0xffffffffu, v, k);
            float4 hv = *reinterpret_cast<const float4*>(&hin[cc * W_OUT + lane * 4]);
            agg.x += vv * hv.x; agg.y += vv * hv.y;
            agg.z += vv * hv.z; agg.w += vv * hv.w;
        }
    }
    float4 td = *reinterpret_cast<const float4*>(&d_tilde[w * W_OUT + lane * 4]);
    float4 o;
    o.x = (1.f - ALPHA_F) * agg.x + ALPHA_F * td.x;
    o.y = (1.f - ALPHA_F) * agg.y + ALPHA_F * td.y;
    o.z = (1.f - ALPHA_F) * agg.z + ALPHA_F * td.z;
    o.w = (1.f - ALPHA_F) * agg.w + ALPHA_F * td.w;
    *reinterpret_cast<float4*>(&hout[w * W_OUT + lane * 4]) = o;
}

// ---------------- renormalize -> Z (into d_out) ----------------
__global__ void renorm_kernel(int finalSel, const int* __restrict__ nt, float* __restrict__ out) {
    const float* __restrict__ hin = buf_ptr(finalSel);
    int q = blockIdx.x * blockDim.x + threadIdx.x;       // float4 index
    if (q >= N_NODES * (W_OUT / 4)) return;
    int node = q >> 5;            // 32 float4 per row
    int fq = q & 31;
    int t = nt[node];
    float4 h = *reinterpret_cast<const float4*>(&hin[node * W_OUT + fq * 4]);
    float4 m = *reinterpret_cast<const float4*>(&d_mean[t * W_OUT + fq * 4]);
    float4 s = *reinterpret_cast<const float4*>(&d_std[t * W_OUT + fq * 4]);
    float4 z;
    z.x = h.x * s.x + m.x; z.y = h.y * s.y + m.y;
    z.z = h.z * s.z + m.z; z.w = h.w * s.w + m.w;
    *reinterpret_cast<float4*>(&out[node * W_OUT + fq * 4]) = z;
}

// ---------------- contrastive loss edge sums ----------------
__global__ void loss_kernel(const int* __restrict__ ei, const int* __restrict__ ne) {
    __shared__ float wp[8], wn[8];
    int gw = (blockIdx.x * blockDim.x + threadIdx.x) >> 5;
    int lane = threadIdx.x & 31;
    int wib = threadIdx.x >> 5;
    float ex = 0.f;
    bool isPos = false;
    if (gw < 2 * E_EDGES) {
        int a, b;
        if (gw < E_EDGES) { a = ei[gw]; b = ei[E_EDGES + gw]; isPos = true; }
        else { int e = gw - E_EDGES; a = ne[e]; b = ne[E_EDGES + e]; }
        float4 za = *reinterpret_cast<const float4*>(&d_z[a * W_OUT + lane * 4]);
        float4 zb = *reinterpret_cast<const float4*>(&d_z[b * W_OUT + lane * 4]);
        float dsum = za.x * zb.x + za.y * zb.y + za.z * zb.z + za.w * zb.w;
#pragma unroll
        for (int off = 16; off; off >>= 1) dsum += __shfl_xor_sync(0xffffffffu, dsum, off);
        ex = expf(dsum * 0.5f);   // / TEMP (=2)
    }
    if (lane == 0) { wp[wib] = isPos ? ex : 0.f; wn[wib] = isPos ? 0.f : ex; }
    __syncthreads();
    if (threadIdx.x == 0) {
        double p = 0.0, n = 0.0;
#pragma unroll
        for (int i = 0; i < 8; i++) { p += (double)wp[i]; n += (double)wn[i]; }
        if (p != 0.0) atomicAdd(&d_posAcc, p);
        if (n != 0.0) atomicAdd(&d_negAcc, n);
    }
}

__global__ void loss_final_kernel(float* __restrict__ out) {
    if (threadIdx.x == 0) {
        double pos = d_posAcc, neg = d_negAcc;
        out[N_NODES * W_OUT] = (float)(-log(pos / (pos + neg)));
    }
}

// ---------------- launch ----------------
extern "C" void kernel_launch(void* const* d_in, const int* in_sizes, int n_in,
                              void* d_out, int out_size) {
    const float* X  = (const float*)d_in[0];
    const float* W  = (const float*)d_in[1];
    const float* b  = (const float*)d_in[2];
    const int*   nt = (const int*)d_in[3];
    const int*   ei = (const int*)d_in[4];  // [2,E] row-major: src = ei, dst = ei+E
    const int*   ne = (const int*)d_in[5];
    float* out = (float*)d_out;

    init_kernel<<<(N_NODES + 255) / 256, 256>>>();
    gemm_l2norm_kernel<<<(N_NODES + GB_NODES - 1) / GB_NODES, 256>>>(X, W, b);
    deg_kernel<<<(E_EDGES + 255) / 256, 256>>>(ei + E_EDGES);
    stats_kernel<<<512, 128>>>(nt);
    finalize_stats_kernel<<<(NUM_TYPES * W_OUT + 127) / 128, 128>>>();
    tilde_kernel<<<(N_NODES + 7) / 8, 256>>>(nt);
    scan1_kernel<<<NB_SCAN, SCAN_B>>>();
    scan2_kernel<<<1, 32>>>();
    scan3_kernel<<<(N_NODES + 255) / 256, 256>>>();
    fill_kernel<<<(E_EDGES + N_NODES + 255) / 256, 256>>>(ei, ei + E_EDGES);

    // APPNP: step 1 reads tilde (0) -> hA (1); then ping-pong hA/hB
    int inSel = 0, outSel = 1;
    for (int k = 0; k < K_STEPS; k++) {
        appnp_kernel<<<(N_NODES + 7) / 8, 256>>>(inSel, outSel);
        if (k == 0) { inSel = 1; outSel = 2; }
        else { int t = inSel; inSel = outSel; outSel = t; }
    }
    int finalSel = outSel == 1 ? 2 : 1;   // buffer written by the last step
    // trace: k0:(0,1) k1:(1,2) k2:(2,1) ... k9:(1,2) -> final in 2
    finalSel = 2;

    renorm_kernel<<<(N_NODES * (W_OUT / 4) + 255) / 256, 256>>>(finalSel, nt, out);
    loss_kernel<<<(2 * E_EDGES + 7) / 8, 256>>>(ei, ne);
    loss_final_kernel<<<1, 32>>>(out);
}

// round 4
// speedup vs baseline: 2.1311x; 2.1311x over previous
#include <cuda_runtime.h>
#include <cuda_fp16.h>
#include <math.h>

#define N_NODES   100000
#define E_EDGES   1600000
#define W_IN      256
#define W_OUT     128
#define NUM_TYPES 4
#define K_STEPS   10
#define ALPHA_F   0.1f
#define EPS_F     1e-12f
#define TOTAL_NNZ (E_EDGES + N_NODES)
#define SCAN_B    1024
#define NB_SCAN   ((N_NODES + SCAN_B - 1) / SCAN_B)

// ---------------- scratch (device globals; no allocation) ----------------
__device__ float  d_H[N_NODES * W_OUT];          // fp32 encoder output
__device__ __half d_t16[N_NODES * W_OUT];        // tilde_H fp16
__device__ __half d_z16[N_NODES * W_OUT];        // l2norm(tilde_H) fp16
__device__ __half d_hA16[N_NODES * W_OUT];
__device__ __half d_hB16[N_NODES * W_OUT];
__device__ int    d_deg[N_NODES];
__device__ int    d_cursor[N_NODES];
__device__ int    d_rowptr[N_NODES + 1];
__device__ int    d_bsum[NB_SCAN];
__device__ int    d_boff[NB_SCAN];
__device__ float  d_dinv[N_NODES];
__device__ int    d_col[TOTAL_NNZ];
__device__ float  d_val[TOTAL_NNZ];
__device__ float  d_tsum[NUM_TYPES * W_OUT];
__device__ float  d_tsq[NUM_TYPES * W_OUT];
__device__ float  d_tcnt[NUM_TYPES];
__device__ float  d_mean[NUM_TYPES * W_OUT];
__device__ float  d_std[NUM_TYPES * W_OUT];
__device__ double d_posAcc;
__device__ double d_negAcc;

// ---------------- init (runs every launch; graph-replay safe) ----------------
__global__ void init_kernel() {
    int i = blockIdx.x * blockDim.x + threadIdx.x;
    if (i < N_NODES) { d_deg[i] = 1; d_cursor[i] = 0; }   // deg starts at 1 (self loop)
    if (i < NUM_TYPES * W_OUT) { d_tsum[i] = 0.f; d_tsq[i] = 0.f; }
    if (i < NUM_TYPES) d_tcnt[i] = 0.f;
    if (i == 0) { d_posAcc = 0.0; d_negAcc = 0.0; }
}

// ---------------- GEMM + bias + row l2norm -> H (fp32) ----------------
#define GB_NODES 64
#define GB_CHUNK 32
__global__ void gemm_l2norm_kernel(const float* __restrict__ X,
                                   const float* __restrict__ W,
                                   const float* __restrict__ b) {
    __shared__ float Ws[GB_CHUNK][W_OUT];
    __shared__ float Xs[GB_NODES][GB_CHUNK + 1];
    int tid = threadIdx.x;
    int fg  = tid & 31;
    int ng  = tid >> 5;
    int nodeBase = blockIdx.x * GB_NODES;

    float4 acc[8];
#pragma unroll
    for (int i = 0; i < 8; i++) acc[i] = make_float4(0.f, 0.f, 0.f, 0.f);

    for (int kc = 0; kc < W_IN; kc += GB_CHUNK) {
#pragma unroll
        for (int j = 0; j < (GB_CHUNK * W_OUT) / 256; j++) {
            int idx = tid + j * 256;
            int kk = idx >> 7, ff = idx & 127;
            Ws[kk][ff] = W[(kc + kk) * W_OUT + ff];
        }
        {
            int kk = tid & 31;
            int r0 = tid >> 5;
#pragma unroll
            for (int j = 0; j < 8; j++) {
                int r = r0 + j * 8;
                int node = nodeBase + r;
                Xs[r][kk] = (node < N_NODES) ? X[node * W_IN + kc + kk] : 0.f;
            }
        }
        __syncthreads();
#pragma unroll
        for (int kk = 0; kk < GB_CHUNK; kk++) {
            float4 w4 = *reinterpret_cast<const float4*>(&Ws[kk][fg * 4]);
#pragma unroll
            for (int i = 0; i < 8; i++) {
                float x = Xs[ng + i * 8][kk];
                acc[i].x += x * w4.x; acc[i].y += x * w4.y;
                acc[i].z += x * w4.z; acc[i].w += x * w4.w;
            }
        }
        __syncthreads();
    }

    float4 b4 = *reinterpret_cast<const float4*>(&b[fg * 4]);
#pragma unroll
    for (int i = 0; i < 8; i++) {
        int node = nodeBase + ng + i * 8;
        float4 h;
        h.x = acc[i].x + b4.x; h.y = acc[i].y + b4.y;
        h.z = acc[i].z + b4.z; h.w = acc[i].w + b4.w;
        float ss = h.x * h.x + h.y * h.y + h.z * h.z + h.w * h.w;
#pragma unroll
        for (int off = 16; off; off >>= 1) ss += __shfl_xor_sync(0xffffffffu, ss, off);
        float inv = 1.f / fmaxf(sqrtf(ss), EPS_F);
        if (node < N_NODES) {
            h.x *= inv; h.y *= inv; h.z *= inv; h.w *= inv;
            *reinterpret_cast<float4*>(&d_H[node * W_OUT + fg * 4]) = h;
        }
    }
}

// ---------------- per-type stats: type-specialized warps ----------------
// Each warp owns one node type; each H row is loaded by exactly one warp chip-wide.
#define ST_BLOCKS 512
__global__ void stats_kernel(const int* __restrict__ nt) {
    __shared__ float s_sum[NUM_TYPES * W_OUT];
    __shared__ float s_sq[NUM_TYPES * W_OUT];
    __shared__ float s_cnt[NUM_TYPES];
    int tid = threadIdx.x;
    for (int i = tid; i < NUM_TYPES * W_OUT; i += 256) { s_sum[i] = 0.f; s_sq[i] = 0.f; }
    if (tid < NUM_TYPES) s_cnt[tid] = 0.f;
    __syncthreads();

    int w = tid >> 5;          // 0..7
    int lane = tid & 31;
    int tt = w & 3;            // this warp's type
    int wslot = blockIdx.x * 2 + (w >> 2);       // 0 .. ST_BLOCKS*2-1 per type
    const int stride = ST_BLOCKS * 2;

    float4 sum = make_float4(0.f, 0.f, 0.f, 0.f);
    float4 sq  = make_float4(0.f, 0.f, 0.f, 0.f);
    float cnt = 0.f;
    for (int node = wslot; node < N_NODES; node += stride) {
        if (nt[node] == tt) {
            float4 h = *reinterpret_cast<const float4*>(&d_H[node * W_OUT + lane * 4]);
            sum.x += h.x; sum.y += h.y; sum.z += h.z; sum.w += h.w;
            sq.x += h.x * h.x; sq.y += h.y * h.y; sq.z += h.z * h.z; sq.w += h.w * h.w;
            if (lane == 0) cnt += 1.f;
        }
    }
    int fb = tt * W_OUT + lane * 4;
    atomicAdd(&s_sum[fb + 0], sum.x); atomicAdd(&s_sum[fb + 1], sum.y);
    atomicAdd(&s_sum[fb + 2], sum.z); atomicAdd(&s_sum[fb + 3], sum.w);
    atomicAdd(&s_sq[fb + 0], sq.x);  atomicAdd(&s_sq[fb + 1], sq.y);
    atomicAdd(&s_sq[fb + 2], sq.z);  atomicAdd(&s_sq[fb + 3], sq.w);
    if (lane == 0) atomicAdd(&s_cnt[tt], cnt);
    __syncthreads();
    for (int i = tid; i < NUM_TYPES * W_OUT; i += 256) {
        atomicAdd(&d_tsum[i], s_sum[i]);
        atomicAdd(&d_tsq[i], s_sq[i]);
    }
    if (tid < NUM_TYPES) atomicAdd(&d_tcnt[tid], s_cnt[tid]);
}

__global__ void finalize_stats_kernel() {
    int i = blockIdx.x * blockDim.x + threadIdx.x;
    if (i < NUM_TYPES * W_OUT) {
        int t = i / W_OUT;
        float c = d_tcnt[t];
        float m = d_tsum[i] / c;
        float var = (d_tsq[i] - c * m * m) / (c - 1.f);
        d_mean[i] = m;
        d_std[i] = sqrtf(fmaxf(var, 0.f));
    }
}

// ---------------- tilde_H (fp16) + z (fp16) ----------------
__global__ void tilde_kernel(const int* __restrict__ nt) {
    int w = (blockIdx.x * blockDim.x + threadIdx.x) >> 5;
    int lane = threadIdx.x & 31;
    if (w >= N_NODES) return;
    int t = nt[w];
    float4 h = *reinterpret_cast<const float4*>(&d_H[w * W_OUT + lane * 4]);
    float4 m = *reinterpret_cast<const float4*>(&d_mean[t * W_OUT + lane * 4]);
    float4 s = *reinterpret_cast<const float4*>(&d_std[t * W_OUT + lane * 4]);
    float4 td;
    td.x = (h.x - m.x) / s.x; td.y = (h.y - m.y) / s.y;
    td.z = (h.z - m.z) / s.z; td.w = (h.w - m.w) / s.w;
    __half2 t0 = __floats2half2_rn(td.x, td.y);
    __half2 t1 = __floats2half2_rn(td.z, td.w);
    uint2 tp; tp.x = *reinterpret_cast<unsigned*>(&t0); tp.y = *reinterpret_cast<unsigned*>(&t1);
    reinterpret_cast<uint2*>(d_t16)[w * 32 + lane] = tp;

    float ss = td.x * td.x + td.y * td.y + td.z * td.z + td.w * td.w;
#pragma unroll
    for (int off = 16; off; off >>= 1) ss += __shfl_xor_sync(0xffffffffu, ss, off);
    float inv = 1.f / fmaxf(sqrtf(ss), EPS_F);
    __half2 z0 = __floats2half2_rn(td.x * inv, td.y * inv);
    __half2 z1 = __floats2half2_rn(td.z * inv, td.w * inv);
    uint2 zp; zp.x = *reinterpret_cast<unsigned*>(&z0); zp.y = *reinterpret_cast<unsigned*>(&z1);
    reinterpret_cast<uint2*>(d_z16)[w * 32 + lane] = zp;
}

// ---------------- degree histogram ----------------
__global__ void deg_kernel(const int* __restrict__ dst) {
    int e = blockIdx.x * blockDim.x + threadIdx.x;
    if (e < E_EDGES) atomicAdd(&d_deg[dst[e]], 1);
}

// ---------------- prefix scan -> rowptr ----------------
__global__ void scan1_kernel() {
    __shared__ int s[SCAN_B];
    int tid = threadIdx.x;
    int i = blockIdx.x * SCAN_B + tid;
    int v = (i < N_NODES) ? d_deg[i] : 0;
    s[tid] = v;
    __syncthreads();
    for (int off = 1; off < SCAN_B; off <<= 1) {
        int t = (tid >= off) ? s[tid - off] : 0;
        __syncthreads();
        s[tid] += t;
        __syncthreads();
    }
    if (i < N_NODES) d_rowptr[i] = s[tid] - v;
    if (tid == SCAN_B - 1) d_bsum[blockIdx.x] = s[SCAN_B - 1];
}

__global__ void scan2_kernel() {
    if (threadIdx.x == 0) {
        int run = 0;
        for (int b = 0; b < NB_SCAN; b++) { d_boff[b] = run; run += d_bsum[b]; }
        d_rowptr[N_NODES] = run;
    }
}

__global__ void scan3_kernel() {
    int i = blockIdx.x * blockDim.x + threadIdx.x;
    if (i < N_NODES) {
        d_rowptr[i] += d_boff[i >> 10];
        d_dinv[i] = rsqrtf((float)d_deg[i]);
    }
}

// ---------------- CSR fill ----------------
__global__ void fill_kernel(const int* __restrict__ src, const int* __restrict__ dst) {
    int i = blockIdx.x * blockDim.x + threadIdx.x;
    if (i < E_EDGES) {
        int s = src[i], d = dst[i];
        int p = d_rowptr[d] + atomicAdd(&d_cursor[d], 1);
        d_col[p] = s;
        d_val[p] = d_dinv[s] * d_dinv[d];
    } else if (i < E_EDGES + N_NODES) {
        int n = i - E_EDGES;
        int p = d_rowptr[n] + atomicAdd(&d_cursor[n], 1);
        d_col[p] = n;
        d_val[p] = d_dinv[n] * d_dinv[n];
    }
}

// ---------------- APPNP step (fp16 state, fp32 accumulate) ----------------
__device__ __forceinline__ __half* buf16_ptr(int sel) {
    return sel == 0 ? d_t16 : (sel == 1 ? d_hA16 : d_hB16);
}

__device__ __forceinline__ void gather_fma(const uint2* __restrict__ hin,
                                           int cc, float vv, int lane, float4& agg) {
    uint2 l = __ldg(&hin[cc * 32 + lane]);
    __half2 h0 = *reinterpret_cast<__half2*>(&l.x);
    __half2 h1 = *reinterpret_cast<__half2*>(&l.y);
    float2 f0 = __half22float2(h0);
    float2 f1 = __half22float2(h1);
    agg.x += vv * f0.x; agg.y += vv * f0.y;
    agg.z += vv * f1.x; agg.w += vv * f1.y;
}

__global__ void appnp_kernel(int inSel, int outSel) {
    const uint2* __restrict__ hin = reinterpret_cast<const uint2*>(buf16_ptr(inSel));
    uint2* __restrict__ hout = reinterpret_cast<uint2*>(buf16_ptr(outSel));
    int w = (blockIdx.x * blockDim.x + threadIdx.x) >> 5;
    int lane = threadIdx.x & 31;
    if (w >= N_NODES) return;
    int start = d_rowptr[w], end = d_rowptr[w + 1];
    float4 agg = make_float4(0.f, 0.f, 0.f, 0.f);
    for (int base = start; base < end; base += 32) {
        int j = base + lane;
        int c = 0; float v = 0.f;
        if (j < end) { c = d_col[j]; v = d_val[j]; }
        int m = min(32, end - base);
        int k = 0;
        for (; k + 4 <= m; k += 4) {
            int cc0 = __shfl_sync(0xffffffffu, c, k + 0);
            int cc1 = __shfl_sync(0xffffffffu, c, k + 1);
            int cc2 = __shfl_sync(0xffffffffu, c, k + 2);
            int cc3 = __shfl_sync(0xffffffffu, c, k + 3);
            float v0 = __shfl_sync(0xffffffffu, v, k + 0);
            float v1 = __shfl_sync(0xffffffffu, v, k + 1);
            float v2 = __shfl_sync(0xffffffffu, v, k + 2);
            float v3 = __shfl_sync(0xffffffffu, v, k + 3);
            uint2 l0 = __ldg(&hin[cc0 * 32 + lane]);
            uint2 l1 = __ldg(&hin[cc1 * 32 + lane]);
            uint2 l2 = __ldg(&hin[cc2 * 32 + lane]);
            uint2 l3 = __ldg(&hin[cc3 * 32 + lane]);
#define ACCUM(L, V) { \
            __half2 h0 = *reinterpret_cast<__half2*>(&L.x); \
            __half2 h1 = *reinterpret_cast<__half2*>(&L.y); \
            float2 f0 = __half22float2(h0); \
            float2 f1 = __half22float2(h1); \
            agg.x += (V) * f0.x; agg.y += (V) * f0.y; \
            agg.z += (V) * f1.x; agg.w += (V) * f1.y; }
            ACCUM(l0, v0) ACCUM(l1, v1) ACCUM(l2, v2) ACCUM(l3, v3)
#undef ACCUM
        }
        for (; k < m; k++) {
            int cc = __shfl_sync(0xffffffffu, c, k);
            float vv = __shfl_sync(0xffffffffu, v, k);
            gather_fma(hin, cc, vv, lane, agg);
        }
    }
    uint2 tp = reinterpret_cast<const uint2*>(d_t16)[w * 32 + lane];
    __half2 t0 = *reinterpret_cast<__half2*>(&tp.x);
    __half2 t1 = *reinterpret_cast<__half2*>(&tp.y);
    float2 tf0 = __half22float2(t0);
    float2 tf1 = __half22float2(t1);
    float4 o;
    o.x = (1.f - ALPHA_F) * agg.x + ALPHA_F * tf0.x;
    o.y = (1.f - ALPHA_F) * agg.y + ALPHA_F * tf0.y;
    o.z = (1.f - ALPHA_F) * agg.z + ALPHA_F * tf1.x;
    o.w = (1.f - ALPHA_F) * agg.w + ALPHA_F * tf1.y;
    __half2 o0 = __floats2half2_rn(o.x, o.y);
    __half2 o1 = __floats2half2_rn(o.z, o.w);
    uint2 st; st.x = *reinterpret_cast<unsigned*>(&o0); st.y = *reinterpret_cast<unsigned*>(&o1);
    hout[w * 32 + lane] = st;
}

// ---------------- renormalize -> Z ----------------
__global__ void renorm_kernel(int finalSel, const int* __restrict__ nt, float* __restrict__ out) {
    const uint2* __restrict__ hin = reinterpret_cast<const uint2*>(buf16_ptr(finalSel));
    int q = blockIdx.x * blockDim.x + threadIdx.x;
    if (q >= N_NODES * 32) return;
    int node = q >> 5;
    int fq = q & 31;
    int t = nt[node];
    uint2 hp = hin[q];
    __half2 h0 = *reinterpret_cast<__half2*>(&hp.x);
    __half2 h1 = *reinterpret_cast<__half2*>(&hp.y);
    float2 f0 = __half22float2(h0);
    float2 f1 = __half22float2(h1);
    float4 m = *reinterpret_cast<const float4*>(&d_mean[t * W_OUT + fq * 4]);
    float4 s = *reinterpret_cast<const float4*>(&d_std[t * W_OUT + fq * 4]);
    float4 z;
    z.x = f0.x * s.x + m.x; z.y = f0.y * s.y + m.y;
    z.z = f1.x * s.z + m.z; z.w = f1.y * s.w + m.w;
    *reinterpret_cast<float4*>(&out[node * W_OUT + fq * 4]) = z;
}

// ---------------- contrastive loss (fp16 z, 16 lanes/edge, smem index staging) ----------------
__global__ void loss_kernel(const int* __restrict__ ei, const int* __restrict__ ne) {
    __shared__ int s_a[256];
    __shared__ int s_b[256];
    __shared__ float s_wp[8], s_wn[8];
    int tid = threadIdx.x;
    int gid = blockIdx.x * 256 + tid;     // global edge id across pos+neg
    {
        int a, b;
        if (gid < E_EDGES) { a = ei[gid]; b = ei[E_EDGES + gid]; }
        else { int e = gid - E_EDGES; a = ne[e]; b = ne[E_EDGES + e]; }
        s_a[tid] = a; s_b[tid] = b;
    }
    __syncthreads();

    int w = tid >> 5;
    int lane = tid & 31;
    int half = lane >> 4;      // 0 or 1: which of the 2 edges in this iteration
    int sub = lane & 15;       // feature slot (16B each, 16 x 16B = 256B row)
    const uint4* __restrict__ z = reinterpret_cast<const uint4*>(d_z16);
    int blockBase = blockIdx.x * 256;

    float accP = 0.f, accN = 0.f;
#pragma unroll 4
    for (int it = 0; it < 16; it++) {
        int slot = w * 32 + it * 2 + half;
        int a = s_a[slot], b = s_b[slot];
        uint4 za = __ldg(&z[a * 16 + sub]);
        uint4 zb = __ldg(&z[b * 16 + sub]);
        __half2 acc = __float2half2_rn(0.f);
        acc = __hfma2(*reinterpret_cast<__half2*>(&za.x), *reinterpret_cast<__half2*>(&zb.x), acc);
        acc = __hfma2(*reinterpret_cast<__half2*>(&za.y), *reinterpret_cast<__half2*>(&zb.y), acc);
        acc = __hfma2(*reinterpret_cast<__half2*>(&za.z), *reinterpret_cast<__half2*>(&zb.z), acc);
        acc = __hfma2(*reinterpret_cast<__half2*>(&za.w), *reinterpret_cast<__half2*>(&zb.w), acc);
        float ds = __low2float(acc) + __high2float(acc);
#pragma unroll
        for (int off = 8; off; off >>= 1) ds += __shfl_xor_sync(0xffffffffu, ds, off);
        if (sub == 0) {
            float ex = exp2f(ds * 0.72134752044f);   // exp(ds/2)
            if (blockBase + slot < E_EDGES) accP += ex; else accN += ex;
        }
    }
#pragma unroll
    for (int off = 16; off; off >>= 1) {
        accP += __shfl_xor_sync(0xffffffffu, accP, off);
        accN += __shfl_xor_sync(0xffffffffu, accN, off);
    }
    if (lane == 0) { s_wp[w] = accP; s_wn[w] = accN; }
    __syncthreads();
    if (tid == 0) {
        double p = 0.0, n = 0.0;
#pragma unroll
        for (int i = 0; i < 8; i++) { p += (double)s_wp[i]; n += (double)s_wn[i]; }
        if (p != 0.0) atomicAdd(&d_posAcc, p);
        if (n != 0.0) atomicAdd(&d_negAcc, n);
    }
}

__global__ void loss_final_kernel(float* __restrict__ out) {
    if (threadIdx.x == 0) {
        double pos = d_posAcc, neg = d_negAcc;
        out[N_NODES * W_OUT] = (float)(-log(pos / (pos + neg)));
    }
}

// ---------------- launch ----------------
extern "C" void kernel_launch(void* const* d_in, const int* in_sizes, int n_in,
                              void* d_out, int out_size) {
    const float* X  = (const float*)d_in[0];
    const float* W  = (const float*)d_in[1];
    const float* b  = (const float*)d_in[2];
    const int*   nt = (const int*)d_in[3];
    const int*   ei = (const int*)d_in[4];
    const int*   ne = (const int*)d_in[5];
    float* out = (float*)d_out;

    init_kernel<<<(N_NODES + 255) / 256, 256>>>();
    gemm_l2norm_kernel<<<(N_NODES + GB_NODES - 1) / GB_NODES, 256>>>(X, W, b);
    deg_kernel<<<(E_EDGES + 255) / 256, 256>>>(ei + E_EDGES);
    stats_kernel<<<ST_BLOCKS, 256>>>(nt);
    finalize_stats_kernel<<<(NUM_TYPES * W_OUT + 127) / 128, 128>>>();
    tilde_kernel<<<(N_NODES + 7) / 8, 256>>>(nt);
    scan1_kernel<<<NB_SCAN, SCAN_B>>>();
    scan2_kernel<<<1, 32>>>();
    scan3_kernel<<<(N_NODES + 255) / 256, 256>>>();
    fill_kernel<<<(E_EDGES + N_NODES + 255) / 256, 256>>>(ei, ei + E_EDGES);

    // APPNP: k0: t16(0) -> A(1); then ping-pong A/B; final ends in B(2)
    int inSel = 0, outSel = 1;
    for (int k = 0; k < K_STEPS; k++) {
        appnp_kernel<<<(N_NODES + 7) / 8, 256>>>(inSel, outSel);
        if (k == 0) { inSel = 1; outSel = 2; }
        else { int t = inSel; inSel = outSel; outSel = t; }
    }

    renorm_kernel<<<(N_NODES * 32 + 255) / 256, 256>>>(2, nt, out);
    loss_kernel<<<(2 * E_EDGES) / 256, 256>>>(ei, ne);
    loss_final_kernel<<<1, 32>>>(out);
}